// round 16
// baseline (speedup 1.0000x reference)
#include <cuda_runtime.h>
#include <cuda_bf16.h>
#include <cuda_fp16.h>
#include <cstdint>

// Tree-RNN GEMMs on mma.sync tensor cores.
// Leaf: fp16 single-term 128x128 tile (R14-proven).
// m=4096/2048: fp16 single-term 128x64 tile (m=2048 emits bf16 hi/lo pair).
// Tail (m<=1024, 11 levels): bf16x3 split-K(8) with fused finalize.

// ---------------- device scratch (no allocation allowed) ----------------
__device__ __half g_leaf16[8192ull * 4096];          // 64 MB
__device__ __half g_We16[512 * 4096];
__device__ __half g_Wc16[512 * 1024];
__device__ __nv_bfloat16 g_Wcb_h[512 * 1024], g_Wcb_l[512 * 1024];
__device__ __half g_P16[8192 * 512];
__device__ __half g_Q16[4096 * 512];
__device__ __nv_bfloat16 g_hB[2048 * 512], g_lB[2048 * 512];
__device__ __nv_bfloat16 g_hC[1024 * 512], g_lC[1024 * 512];
#define KSPLIT 8
__device__ float g_part[KSPLIT * 1024 * 512];        // 16 MB
__device__ unsigned g_ticket[256];                   // zero-init, self-reset

// ---------------- PTX helpers ----------------
__device__ __forceinline__ void mma_bf16(float c[4], const uint32_t a[4],
                                         const uint32_t b0, const uint32_t b1) {
    asm volatile(
        "mma.sync.aligned.m16n8k16.row.col.f32.bf16.bf16.f32 "
        "{%0,%1,%2,%3}, {%4,%5,%6,%7}, {%8,%9}, {%0,%1,%2,%3};\n"
        : "+f"(c[0]), "+f"(c[1]), "+f"(c[2]), "+f"(c[3])
        : "r"(a[0]), "r"(a[1]), "r"(a[2]), "r"(a[3]), "r"(b0), "r"(b1));
}
__device__ __forceinline__ void mma_fp16(float c[4], const uint32_t a[4],
                                         const uint32_t b0, const uint32_t b1) {
    asm volatile(
        "mma.sync.aligned.m16n8k16.row.col.f32.f16.f16.f32 "
        "{%0,%1,%2,%3}, {%4,%5,%6,%7}, {%8,%9}, {%0,%1,%2,%3};\n"
        : "+f"(c[0]), "+f"(c[1]), "+f"(c[2]), "+f"(c[3])
        : "r"(a[0]), "r"(a[1]), "r"(a[2]), "r"(a[3]), "r"(b0), "r"(b1));
}
__device__ __forceinline__ void cp16(uint32_t dst, const void* src, bool p) {
    asm volatile("cp.async.cg.shared.global [%0], [%1], 16, %2;"
                 :: "r"(dst), "l"(src), "r"(p ? 16 : 0));
}
__device__ __forceinline__ void cp_commit() {
    asm volatile("cp.async.commit_group;");
}
template <int N> __device__ __forceinline__ void cp_wait() {
    asm volatile("cp.async.wait_group %0;" :: "n"(N));
}
__device__ __forceinline__ void ldsm4(uint32_t r[4], uint32_t a) {
    asm volatile("ldmatrix.sync.aligned.m8n8.x4.shared.b16 {%0,%1,%2,%3}, [%4];"
                 : "=r"(r[0]), "=r"(r[1]), "=r"(r[2]), "=r"(r[3]) : "r"(a));
}
__device__ __forceinline__ uint32_t pack_bf2(__nv_bfloat16 a, __nv_bfloat16 b) {
    __nv_bfloat162 t{a, b};
    return *reinterpret_cast<uint32_t*>(&t);
}
__device__ __forceinline__ uint32_t pack_h2(__half a, __half b) {
    __half2 t{a, b};
    return *reinterpret_cast<uint32_t*>(&t);
}

// ---------------- convert/split kernels ----------------
__global__ void conv_f16(const float4* __restrict__ src,
                         uint2* __restrict__ out, int n4)
{
    int i = blockIdx.x * blockDim.x + threadIdx.x;
    const int stride = gridDim.x * blockDim.x;
    for (; i < n4; i += stride) {
        float4 v = src[i];
        uint2 o;
        o.x = pack_h2(__float2half_rn(v.x), __float2half_rn(v.y));
        o.y = pack_h2(__float2half_rn(v.z), __float2half_rn(v.w));
        out[i] = o;
    }
}
__global__ void split_wc(const float4* __restrict__ src,
                         uint2* __restrict__ w16,
                         uint2* __restrict__ hbf, uint2* __restrict__ lbf,
                         int n4)
{
    int i = blockIdx.x * blockDim.x + threadIdx.x;
    const int stride = gridDim.x * blockDim.x;
    for (; i < n4; i += stride) {
        float4 v = src[i];
        uint2 F;
        F.x = pack_h2(__float2half_rn(v.x), __float2half_rn(v.y));
        F.y = pack_h2(__float2half_rn(v.z), __float2half_rn(v.w));
        w16[i] = F;
        __nv_bfloat16 b0 = __float2bfloat16(v.x), b1 = __float2bfloat16(v.y);
        __nv_bfloat16 b2 = __float2bfloat16(v.z), b3 = __float2bfloat16(v.w);
        uint2 BH, BL;
        BH.x = pack_bf2(b0, b1);
        BH.y = pack_bf2(b2, b3);
        BL.x = pack_bf2(__float2bfloat16(v.x - __bfloat162float(b0)),
                        __float2bfloat16(v.y - __bfloat162float(b1)));
        BL.y = pack_bf2(__float2bfloat16(v.z - __bfloat162float(b2)),
                        __float2bfloat16(v.w - __bfloat162float(b3)));
        hbf[i] = BH;
        lbf[i] = BL;
    }
}

// ============================================================================
// gemmh128: fp16 single-term, 128x128 CTA tile, warp 32x64 (R14-proven).
// ============================================================================
#define B128_OFF 16384
#define STAGE128 32768
#define SMEM128 (3 * STAGE128)

__global__ __launch_bounds__(256, 2)
void gemmh128(const __half* __restrict__ A,
              const __half* __restrict__ W,
              const float* __restrict__ bias,
              __half* __restrict__ Cf16,
              int M, int N, int K)
{
    extern __shared__ __align__(1024) char smem[];
    const uint32_t sbase = (uint32_t)__cvta_generic_to_shared(smem);

    const int tid  = threadIdx.x;
    const int lane = tid & 31;
    const int wid  = tid >> 5;
    const int wm   = (wid & 3) * 32;
    const int wn   = (wid >> 2) * 64;
    const int bm   = blockIdx.y * 128;
    const int bn   = blockIdx.x * 128;

    const int lr8   = lane & 7;
    const int g     = lane >> 3;
    const int mrow  = (g & 1) * 8;
    const int kcolB = (g >> 1) * 16;

    uint32_t aRow[2], aXm[2], bRow[4], bXm[4];
    #pragma unroll
    for (int mi = 0; mi < 2; mi++) {
        const uint32_t rB = (uint32_t)(wm + mi * 16 + mrow + lr8) * 128;
        aRow[mi] = rB;
        aXm[mi]  = (rB >> 3) & 0x70;
    }
    #pragma unroll
    for (int p = 0; p < 4; p++) {
        const uint32_t rB = (uint32_t)(wn + p * 16 + mrow + lr8) * 128;
        bRow[p] = B128_OFF + rB;
        bXm[p]  = (rB >> 3) & 0x70;
    }

    float acc[2][8][4];
    #pragma unroll
    for (int i = 0; i < 2; i++)
        #pragma unroll
        for (int j = 0; j < 8; j++)
            #pragma unroll
            for (int v = 0; v < 4; v++) acc[i][j][v] = 0.f;

    const int nT = K / 64;

    auto stage = [&](int lt) {
        const uint32_t sb = sbase + (uint32_t)(lt % 3) * STAGE128;
        const int k0 = lt * 64;
        #pragma unroll
        for (int i = 0; i < 4; i++) {
            const int lin = tid + i * 256;
            const int r = lin >> 3;
            const int c = lin & 7;
            const uint32_t off = (uint32_t)r * 128 + (uint32_t)c * 16;
            const uint32_t sw = off ^ ((off >> 3) & 0x70);
            const bool pa = (bm + r) < M;
            cp16(sb + sw, A + (size_t)(bm + r) * K + k0 + c * 8, pa);
        }
        #pragma unroll
        for (int i = 0; i < 4; i++) {
            const int lin = tid + i * 256;
            const int r = lin >> 3;
            const int c = lin & 7;
            const uint32_t off = (uint32_t)r * 128 + (uint32_t)c * 16;
            const uint32_t sw = off ^ ((off >> 3) & 0x70);
            cp16(sb + B128_OFF + sw, W + (size_t)(bn + r) * K + k0 + c * 8, true);
        }
        cp_commit();
    };

    stage(0);
    stage(1);

    for (int kt = 0; kt < nT; kt++) {
        if (kt + 1 < nT) cp_wait<1>();
        else             cp_wait<0>();
        __syncthreads();
        if (kt + 2 < nT) stage(kt + 2);

        const uint32_t s0 = sbase + (uint32_t)(kt % 3) * STAGE128;

        #pragma unroll
        for (int ks = 0; ks < 64; ks += 16) {
            const uint32_t col = (uint32_t)(ks * 2) + kcolB;
            uint32_t ah[2][4];
            #pragma unroll
            for (int mi = 0; mi < 2; mi++)
                ldsm4(ah[mi], s0 + aRow[mi] + (col ^ aXm[mi]));
            #pragma unroll
            for (int p = 0; p < 4; p++) {
                uint32_t bh[4];
                ldsm4(bh, s0 + bRow[p] + (col ^ bXm[p]));
                #pragma unroll
                for (int mi = 0; mi < 2; mi++) {
                    mma_fp16(acc[mi][2 * p],     ah[mi], bh[0], bh[2]);
                    mma_fp16(acc[mi][2 * p + 1], ah[mi], bh[1], bh[3]);
                }
            }
        }
    }

    const int lq = (lane & 3) * 2;
    const int lr = lane >> 2;
    #pragma unroll
    for (int mi = 0; mi < 2; mi++) {
        #pragma unroll
        for (int ni = 0; ni < 8; ni++) {
            const int m0 = bm + wm + mi * 16 + lr;
            const int n  = bn + wn + ni * 8 + lq;
            const float bv0 = __ldg(bias + n), bv1 = __ldg(bias + n + 1);
            #pragma unroll
            for (int h = 0; h < 2; h++) {
                const int m = m0 + h * 8;
                if (m < M) {
                    float x0 = fmaxf(acc[mi][ni][2 * h]     + bv0, 0.f);
                    float x1 = fmaxf(acc[mi][ni][2 * h + 1] + bv1, 0.f);
                    *reinterpret_cast<uint32_t*>(Cf16 + (size_t)m * N + n) =
                        pack_h2(__float2half_rn(x0), __float2half_rn(x1));
                }
            }
        }
    }
}

// ============================================================================
// gemmh<OUT>: fp16 single-term, 128x64 tile (R13-proven).
// ============================================================================
#define BH_OFF 16384
#define STAGEH 24576
#define SMEMH (4 * STAGEH)

template <int OUT>
__global__ __launch_bounds__(256, 2)
void gemmh(const __half* __restrict__ A,
           const __half* __restrict__ W,
           const float* __restrict__ bias,
           __half* __restrict__ Cf16,
           __nv_bfloat16* __restrict__ Chi,
           __nv_bfloat16* __restrict__ Clo,
           int M, int N, int K)
{
    extern __shared__ __align__(1024) char smem[];
    const uint32_t sbase = (uint32_t)__cvta_generic_to_shared(smem);

    const int tid  = threadIdx.x;
    const int lane = tid & 31;
    const int wid  = tid >> 5;
    const int wm   = (wid & 3) * 32;
    const int wn   = (wid >> 2) * 32;
    const int bm   = blockIdx.y * 128;
    const int bn   = blockIdx.x * 64;

    const int lr8   = lane & 7;
    const int g     = lane >> 3;
    const int mrow  = (g & 1) * 8;
    const int kcolB = (g >> 1) * 16;

    uint32_t aRow[2], aXm[2], bRow[2], bXm[2];
    #pragma unroll
    for (int mi = 0; mi < 2; mi++) {
        const uint32_t rB = (uint32_t)(wm + mi * 16 + mrow + lr8) * 128;
        aRow[mi] = rB;
        aXm[mi]  = (rB >> 3) & 0x70;
    }
    #pragma unroll
    for (int p = 0; p < 2; p++) {
        const uint32_t rB = (uint32_t)(wn + p * 16 + mrow + lr8) * 128;
        bRow[p] = BH_OFF + rB;
        bXm[p]  = (rB >> 3) & 0x70;
    }

    float acc[2][4][4];
    #pragma unroll
    for (int i = 0; i < 2; i++)
        #pragma unroll
        for (int j = 0; j < 4; j++)
            #pragma unroll
            for (int v = 0; v < 4; v++) acc[i][j][v] = 0.f;

    const int nT = K / 64;

    auto stage = [&](int lt) {
        const uint32_t sb = sbase + (uint32_t)(lt & 3) * STAGEH;
        const int k0 = lt * 64;
        #pragma unroll
        for (int i = 0; i < 4; i++) {
            const int lin = tid + i * 256;
            const int r = lin >> 3;
            const int c = lin & 7;
            const uint32_t off = (uint32_t)r * 128 + (uint32_t)c * 16;
            const uint32_t sw = off ^ ((off >> 3) & 0x70);
            const bool pa = (bm + r) < M;
            cp16(sb + sw, A + (size_t)(bm + r) * K + k0 + c * 8, pa);
        }
        #pragma unroll
        for (int i = 0; i < 2; i++) {
            const int lin = tid + i * 256;
            const int r = lin >> 3;
            const int c = lin & 7;
            const uint32_t off = (uint32_t)r * 128 + (uint32_t)c * 16;
            const uint32_t sw = off ^ ((off >> 3) & 0x70);
            cp16(sb + BH_OFF + sw, W + (size_t)(bn + r) * K + k0 + c * 8, true);
        }
        cp_commit();
    };

    stage(0);
    stage(1);
    stage(2);

    for (int kt = 0; kt < nT; kt++) {
        if (kt + 2 <= nT - 1)      cp_wait<2>();
        else if (kt + 1 <= nT - 1) cp_wait<1>();
        else                       cp_wait<0>();
        __syncthreads();
        if (kt + 3 < nT) stage(kt + 3);

        const uint32_t s0 = sbase + (uint32_t)(kt & 3) * STAGEH;

        #pragma unroll
        for (int ks = 0; ks < 64; ks += 16) {
            const uint32_t col = (uint32_t)(ks * 2) + kcolB;
            uint32_t ah[2][4], bh[2][4];
            #pragma unroll
            for (int mi = 0; mi < 2; mi++)
                ldsm4(ah[mi], s0 + aRow[mi] + (col ^ aXm[mi]));
            #pragma unroll
            for (int p = 0; p < 2; p++)
                ldsm4(bh[p], s0 + bRow[p] + (col ^ bXm[p]));
            #pragma unroll
            for (int mi = 0; mi < 2; mi++)
                #pragma unroll
                for (int ni = 0; ni < 4; ni++) {
                    const int p = ni >> 1, q = ni & 1;
                    mma_fp16(acc[mi][ni], ah[mi], bh[p][q], bh[p][q + 2]);
                }
        }
    }

    const int lq = (lane & 3) * 2;
    const int lr = lane >> 2;
    #pragma unroll
    for (int mi = 0; mi < 2; mi++) {
        #pragma unroll
        for (int ni = 0; ni < 4; ni++) {
            const int m0 = bm + wm + mi * 16 + lr;
            const int n  = bn + wn + ni * 8 + lq;
            const float bv0 = __ldg(bias + n), bv1 = __ldg(bias + n + 1);
            #pragma unroll
            for (int h = 0; h < 2; h++) {
                const int m = m0 + h * 8;
                if (m < M) {
                    float x0 = fmaxf(acc[mi][ni][2 * h]     + bv0, 0.f);
                    float x1 = fmaxf(acc[mi][ni][2 * h + 1] + bv1, 0.f);
                    if (OUT == 0) {
                        *reinterpret_cast<uint32_t*>(Cf16 + (size_t)m * N + n) =
                            pack_h2(__float2half_rn(x0), __float2half_rn(x1));
                    } else {
                        __nv_bfloat16 h0 = __float2bfloat16(x0);
                        __nv_bfloat16 h1 = __float2bfloat16(x1);
                        __nv_bfloat16 l0 = __float2bfloat16(x0 - __bfloat162float(h0));
                        __nv_bfloat16 l1 = __float2bfloat16(x1 - __bfloat162float(h1));
                        *reinterpret_cast<uint32_t*>(Chi + (size_t)m * N + n) = pack_bf2(h0, h1);
                        *reinterpret_cast<uint32_t*>(Clo + (size_t)m * N + n) = pack_bf2(l0, l1);
                    }
                }
            }
        }
    }
}

// ============================================================================
// gemm_small_fused: bf16x3 split-K(8) with fused finalize.
// 32x64 tile, 128 threads, grid (N/64, ceil(M/32), KSPLIT). K/KSPLIT=128,
// nT=4. Last-arriving z-CTA per tile sums 8 partials in fixed z order.
// ============================================================================
#define A_T3 4096
#define STAGE3 12288
#define SMEM3 (3 * STAGE3)

__global__ __launch_bounds__(128, 4)
void gemm_small_fused(const __nv_bfloat16* __restrict__ Ahi,
                      const __nv_bfloat16* __restrict__ Alo,
                      const __nv_bfloat16* __restrict__ Whi,
                      const __nv_bfloat16* __restrict__ Wlo,
                      const float* __restrict__ bias,
                      float* __restrict__ part,
                      unsigned* __restrict__ ticket,
                      __nv_bfloat16* __restrict__ Chi,
                      __nv_bfloat16* __restrict__ Clo,
                      int M, int N, int K)
{
    extern __shared__ __align__(1024) char smem[];
    const uint32_t sbase = (uint32_t)__cvta_generic_to_shared(smem);

    const int tid  = threadIdx.x;
    const int lane = tid & 31;
    const int wid  = tid >> 5;
    const int wm   = (wid & 1) * 16;
    const int wn   = (wid >> 1) * 32;
    const int bm   = blockIdx.y * 32;
    const int bn   = blockIdx.x * 64;
    const int kbase = blockIdx.z * (K / KSPLIT);

    const int lr8   = lane & 7;
    const int g     = lane >> 3;
    const int mrow  = (g & 1) * 8;
    const int kcolB = (g >> 1) * 16;

    uint32_t aRowB, aXm, bRow[2], bXm[2];
    {
        const uint32_t rB = (uint32_t)(wm + mrow + lr8) * 128;
        aRowB = rB;
        aXm   = (rB >> 3) & 0x70;
    }
    #pragma unroll
    for (int p = 0; p < 2; p++) {
        const uint32_t rB = (uint32_t)(wn + p * 16 + mrow + lr8) * 128;
        bRow[p] = A_T3 + rB;
        bXm[p]  = (rB >> 3) & 0x70;
    }

    float acc[4][4];
    #pragma unroll
    for (int j = 0; j < 4; j++)
        #pragma unroll
        for (int v = 0; v < 4; v++) acc[j][v] = 0.f;

    const int nT = (K / KSPLIT) / 32;   // 4

    auto stage = [&](int lt) {
        const uint32_t sb = sbase + (uint32_t)(lt % 3) * STAGE3;
        const int k0 = kbase + lt * 32;
        #pragma unroll
        for (int i = 0; i < 2; i++) {
            const int lin = tid + i * 128;
            const int r = lin >> 3;
            const int c = lin & 7;
            const uint32_t off = (uint32_t)r * 128 + (uint32_t)c * 16;
            const uint32_t sw = off ^ ((off >> 3) & 0x70);
            const bool pa = (bm + r) < M;
            const __nv_bfloat16* src = (c < 4) ? Ahi : Alo;
            cp16(sb + sw, src + (size_t)(bm + r) * K + k0 + (c & 3) * 8, pa);
        }
        #pragma unroll
        for (int i = 0; i < 4; i++) {
            const int lin = tid + i * 128;
            const int r = lin >> 3;
            const int c = lin & 7;
            const uint32_t off = (uint32_t)r * 128 + (uint32_t)c * 16;
            const uint32_t sw = off ^ ((off >> 3) & 0x70);
            const __nv_bfloat16* src = (c < 4) ? Whi : Wlo;
            cp16(sb + A_T3 + sw, src + (size_t)(bn + r) * K + k0 + (c & 3) * 8, true);
        }
        cp_commit();
    };

    stage(0);
    stage(1);

    for (int kt = 0; kt < nT; kt++) {
        if (kt + 1 < nT) cp_wait<1>();
        else             cp_wait<0>();
        __syncthreads();
        if (kt + 2 < nT) stage(kt + 2);

        const uint32_t s0 = sbase + (uint32_t)(kt % 3) * STAGE3;

        #pragma unroll
        for (int ks = 0; ks < 32; ks += 16) {
            const uint32_t colH = (uint32_t)(ks * 2) + kcolB;
            const uint32_t colL = 64u + (uint32_t)(ks * 2) + kcolB;
            uint32_t ah[4], al[4], bh[2][4], bl[2][4];
            ldsm4(ah, s0 + aRowB + (colH ^ aXm));
            ldsm4(al, s0 + aRowB + (colL ^ aXm));
            #pragma unroll
            for (int p = 0; p < 2; p++) {
                ldsm4(bh[p], s0 + bRow[p] + (colH ^ bXm[p]));
                ldsm4(bl[p], s0 + bRow[p] + (colL ^ bXm[p]));
            }
            #pragma unroll
            for (int ni = 0; ni < 4; ni++) {
                const int p = ni >> 1, q = ni & 1;
                mma_bf16(acc[ni], ah, bh[p][q], bh[p][q + 2]);
                mma_bf16(acc[ni], ah, bl[p][q], bl[p][q + 2]);
                mma_bf16(acc[ni], al, bh[p][q], bh[p][q + 2]);
            }
        }
    }

    const int lq = (lane & 3) * 2;
    const int lr = lane >> 2;
    #pragma unroll
    for (int ni = 0; ni < 4; ni++) {
        const int m0 = bm + wm + lr;
        const int n  = bn + wn + ni * 8 + lq;
        #pragma unroll
        for (int h = 0; h < 2; h++) {
            const int m = m0 + h * 8;
            if (m < M) {
                float* dst = part + ((size_t)blockIdx.z * M + m) * N + n;
                dst[0] = acc[ni][2 * h];
                dst[1] = acc[ni][2 * h + 1];
            }
        }
    }

    __threadfence();
    __syncthreads();
    __shared__ unsigned s_old;
    const int tileId = (int)blockIdx.y * (int)gridDim.x + (int)blockIdx.x;
    if (tid == 0) s_old = atomicAdd(&ticket[tileId], 1u);
    __syncthreads();
    if (s_old == KSPLIT - 1) {
        __threadfence();
        for (int idx = tid * 2; idx < 32 * 64; idx += 256) {
            const int lm = idx >> 6;
            const int ln = idx & 63;
            const int m = bm + lm;
            if (m >= M) break;
            const int n = bn + ln;
            float s0 = 0.f, s1 = 0.f;
            #pragma unroll
            for (int z = 0; z < KSPLIT; z++) {
                const float* p = part + ((size_t)z * M + m) * N + n;
                s0 += p[0];
                s1 += p[1];
            }
            float x0 = fmaxf(s0 + __ldg(bias + n), 0.f);
            float x1 = fmaxf(s1 + __ldg(bias + n + 1), 0.f);
            __nv_bfloat16 h0 = __float2bfloat16(x0);
            __nv_bfloat16 h1 = __float2bfloat16(x1);
            __nv_bfloat16 l0 = __float2bfloat16(x0 - __bfloat162float(h0));
            __nv_bfloat16 l1 = __float2bfloat16(x1 - __bfloat162float(h1));
            *reinterpret_cast<uint32_t*>(Chi + (size_t)m * N + n) = pack_bf2(h0, h1);
            *reinterpret_cast<uint32_t*>(Clo + (size_t)m * N + n) = pack_bf2(l0, l1);
        }
        if (tid == 0) ticket[tileId] = 0;
    }
}

// Root projection
__global__ void proj_kernel(const __nv_bfloat16* __restrict__ hhi,
                            const __nv_bfloat16* __restrict__ hlo,
                            const float* __restrict__ Wp,
                            const float* __restrict__ bp,
                            float* __restrict__ out)
{
    const int w    = threadIdx.x >> 5;
    const int lane = threadIdx.x & 31;
    float s = 0.f;
    for (int k = lane; k < 512; k += 32) {
        const float hv = __bfloat162float(hhi[k]) + __bfloat162float(hlo[k]);
        s = fmaf(hv, Wp[w * 512 + k], s);
    }
    #pragma unroll
    for (int o = 16; o > 0; o >>= 1)
        s += __shfl_xor_sync(0xffffffffu, s, o);
    if (lane == 0) out[w] = s + bp[w];
}

extern "C" void kernel_launch(void* const* d_in, const int* in_sizes, int n_in,
                              void* d_out, int out_size)
{
    const float* leaf  = (const float*)d_in[0];
    const float* Wemb  = (const float*)d_in[1];
    const float* bemb  = (const float*)d_in[2];
    const float* Wcomb = (const float*)d_in[3];
    const float* bcomb = (const float*)d_in[4];
    const float* Wproj = (const float*)d_in[5];
    const float* bproj = (const float*)d_in[6];
    float* out = (float*)d_out;

    __half *leaf16, *We16, *Wc16, *P16, *Q16;
    __nv_bfloat16 *Wcb_h, *Wcb_l, *hB, *lB, *hC, *lC;
    float* part;
    unsigned* ticket;
    cudaGetSymbolAddress((void**)&leaf16, g_leaf16);
    cudaGetSymbolAddress((void**)&We16, g_We16);
    cudaGetSymbolAddress((void**)&Wc16, g_Wc16);
    cudaGetSymbolAddress((void**)&Wcb_h, g_Wcb_h);
    cudaGetSymbolAddress((void**)&Wcb_l, g_Wcb_l);
    cudaGetSymbolAddress((void**)&P16, g_P16);
    cudaGetSymbolAddress((void**)&Q16, g_Q16);
    cudaGetSymbolAddress((void**)&hB, g_hB);
    cudaGetSymbolAddress((void**)&lB, g_lB);
    cudaGetSymbolAddress((void**)&hC, g_hC);
    cudaGetSymbolAddress((void**)&lC, g_lC);
    cudaGetSymbolAddress((void**)&part, g_part);
    cudaGetSymbolAddress((void**)&ticket, g_ticket);

    cudaFuncSetAttribute(gemmh128,
                         cudaFuncAttributeMaxDynamicSharedMemorySize, SMEM128);
    cudaFuncSetAttribute(gemmh<0>,
                         cudaFuncAttributeMaxDynamicSharedMemorySize, SMEMH);
    cudaFuncSetAttribute(gemmh<1>,
                         cudaFuncAttributeMaxDynamicSharedMemorySize, SMEMH);
    cudaFuncSetAttribute(gemm_small_fused,
                         cudaFuncAttributeMaxDynamicSharedMemorySize, SMEM3);

    // ---- convert/split inputs ----
    conv_f16<<<4096, 256>>>((const float4*)leaf, (uint2*)leaf16, 8192 * 4096 / 4);
    conv_f16<<<512, 256>>>((const float4*)Wemb, (uint2*)We16, 512 * 4096 / 4);
    split_wc<<<128, 256>>>((const float4*)Wcomb, (uint2*)Wc16,
                           (uint2*)Wcb_h, (uint2*)Wcb_l, 512 * 1024 / 4);

    // ---- leaf -> P16 (128x128 tiles, 256 CTAs) ----
    {
        dim3 grid(512 / 128, 8192 / 128);
        gemmh128<<<grid, 256, SMEM128>>>(leaf16, We16, bemb, P16,
                                         8192, 512, 4096);
    }
    // ---- m = 4096 -> Q16 (128x64 tiles, 256 CTAs) ----
    {
        dim3 grid(512 / 64, 4096 / 128);
        gemmh<0><<<grid, 256, SMEMH>>>(P16, Wc16, bcomb,
                                       Q16, nullptr, nullptr, 4096, 512, 1024);
    }
    // ---- m = 2048 -> bf16 pair hB/lB (128x64 tiles) ----
    {
        dim3 grid(512 / 64, 2048 / 128);
        gemmh<1><<<grid, 256, SMEMH>>>(Q16, Wc16, bcomb,
                                       nullptr, hB, lB, 2048, 512, 1024);
    }

    // ---- tail m = 1024..1: bf16x3 split-K(8) with fused finalize ----
    __nv_bfloat16 *cur_h = hB, *cur_l = lB, *nxt_h = hC, *nxt_l = lC;
    for (int m = 1024; m >= 1; m >>= 1) {
        dim3 grid(512 / 64, (m + 31) / 32, KSPLIT);
        gemm_small_fused<<<grid, 128, SMEM3>>>(cur_h, cur_l, Wcb_h, Wcb_l,
                                               bcomb, part, ticket,
                                               nxt_h, nxt_l, m, 512, 1024);
        __nv_bfloat16* t;
        t = cur_h; cur_h = nxt_h; nxt_h = t;
        t = cur_l; cur_l = nxt_l; nxt_l = t;
    }

    proj_kernel<<<1, 64>>>(cur_h, cur_l, Wproj, bproj, out);
}

// round 17
// speedup vs baseline: 1.0303x; 1.0303x over previous
#include <cuda_runtime.h>
#include <cuda_bf16.h>
#include <cuda_fp16.h>
#include <cstdint>

// Tree-RNN GEMMs on mma.sync tensor cores.
// Leaf: fp16 single-term 128x128 tile (R14-proven, 103us).
// m=4096/2048: fp16 single-term 128x64 tile (256-CTA grids).
// m=1024: 128x64 tile emitting bf16 hi/lo pair.
// Tail (m<=512): bf16x3 split-K(4) with fused finalize (R12-proven).

// ---------------- device scratch (no allocation allowed) ----------------
__device__ __half g_leaf16[8192ull * 4096];          // 64 MB
__device__ __half g_We16[512 * 4096];
__device__ __half g_Wc16[512 * 1024];
__device__ __nv_bfloat16 g_Wcb_h[512 * 1024], g_Wcb_l[512 * 1024];
__device__ __half g_P16[8192 * 512];
__device__ __half g_Q16[4096 * 512];
__device__ __nv_bfloat16 g_hB[1024 * 512], g_lB[1024 * 512];
__device__ __nv_bfloat16 g_hC[512 * 512],  g_lC[512 * 512];
#define KSPLIT 4
__device__ float g_part[KSPLIT * 512 * 512];
__device__ unsigned g_ticket[128];                   // zero-init, self-reset

// ---------------- PTX helpers ----------------
__device__ __forceinline__ void mma_bf16(float c[4], const uint32_t a[4],
                                         const uint32_t b0, const uint32_t b1) {
    asm volatile(
        "mma.sync.aligned.m16n8k16.row.col.f32.bf16.bf16.f32 "
        "{%0,%1,%2,%3}, {%4,%5,%6,%7}, {%8,%9}, {%0,%1,%2,%3};\n"
        : "+f"(c[0]), "+f"(c[1]), "+f"(c[2]), "+f"(c[3])
        : "r"(a[0]), "r"(a[1]), "r"(a[2]), "r"(a[3]), "r"(b0), "r"(b1));
}
__device__ __forceinline__ void mma_fp16(float c[4], const uint32_t a[4],
                                         const uint32_t b0, const uint32_t b1) {
    asm volatile(
        "mma.sync.aligned.m16n8k16.row.col.f32.f16.f16.f32 "
        "{%0,%1,%2,%3}, {%4,%5,%6,%7}, {%8,%9}, {%0,%1,%2,%3};\n"
        : "+f"(c[0]), "+f"(c[1]), "+f"(c[2]), "+f"(c[3])
        : "r"(a[0]), "r"(a[1]), "r"(a[2]), "r"(a[3]), "r"(b0), "r"(b1));
}
__device__ __forceinline__ void cp16(uint32_t dst, const void* src, bool p) {
    asm volatile("cp.async.cg.shared.global [%0], [%1], 16, %2;"
                 :: "r"(dst), "l"(src), "r"(p ? 16 : 0));
}
__device__ __forceinline__ void cp_commit() {
    asm volatile("cp.async.commit_group;");
}
template <int N> __device__ __forceinline__ void cp_wait() {
    asm volatile("cp.async.wait_group %0;" :: "n"(N));
}
__device__ __forceinline__ void ldsm4(uint32_t r[4], uint32_t a) {
    asm volatile("ldmatrix.sync.aligned.m8n8.x4.shared.b16 {%0,%1,%2,%3}, [%4];"
                 : "=r"(r[0]), "=r"(r[1]), "=r"(r[2]), "=r"(r[3]) : "r"(a));
}
__device__ __forceinline__ uint32_t pack_bf2(__nv_bfloat16 a, __nv_bfloat16 b) {
    __nv_bfloat162 t{a, b};
    return *reinterpret_cast<uint32_t*>(&t);
}
__device__ __forceinline__ uint32_t pack_h2(__half a, __half b) {
    __half2 t{a, b};
    return *reinterpret_cast<uint32_t*>(&t);
}

// ---------------- convert/split kernels ----------------
__global__ void conv_f16(const float4* __restrict__ src,
                         uint2* __restrict__ out, int n4)
{
    int i = blockIdx.x * blockDim.x + threadIdx.x;
    const int stride = gridDim.x * blockDim.x;
    for (; i < n4; i += stride) {
        float4 v = src[i];
        uint2 o;
        o.x = pack_h2(__float2half_rn(v.x), __float2half_rn(v.y));
        o.y = pack_h2(__float2half_rn(v.z), __float2half_rn(v.w));
        out[i] = o;
    }
}
__global__ void split_wc(const float4* __restrict__ src,
                         uint2* __restrict__ w16,
                         uint2* __restrict__ hbf, uint2* __restrict__ lbf,
                         int n4)
{
    int i = blockIdx.x * blockDim.x + threadIdx.x;
    const int stride = gridDim.x * blockDim.x;
    for (; i < n4; i += stride) {
        float4 v = src[i];
        uint2 F;
        F.x = pack_h2(__float2half_rn(v.x), __float2half_rn(v.y));
        F.y = pack_h2(__float2half_rn(v.z), __float2half_rn(v.w));
        w16[i] = F;
        __nv_bfloat16 b0 = __float2bfloat16(v.x), b1 = __float2bfloat16(v.y);
        __nv_bfloat16 b2 = __float2bfloat16(v.z), b3 = __float2bfloat16(v.w);
        uint2 BH, BL;
        BH.x = pack_bf2(b0, b1);
        BH.y = pack_bf2(b2, b3);
        BL.x = pack_bf2(__float2bfloat16(v.x - __bfloat162float(b0)),
                        __float2bfloat16(v.y - __bfloat162float(b1)));
        BL.y = pack_bf2(__float2bfloat16(v.z - __bfloat162float(b2)),
                        __float2bfloat16(v.w - __bfloat162float(b3)));
        hbf[i] = BH;
        lbf[i] = BL;
    }
}

// ============================================================================
// gemmh128: fp16 single-term, 128x128 CTA tile, warp 32x64 (R14-proven).
// ============================================================================
#define B128_OFF 16384
#define STAGE128 32768
#define SMEM128 (3 * STAGE128)

__global__ __launch_bounds__(256, 2)
void gemmh128(const __half* __restrict__ A,
              const __half* __restrict__ W,
              const float* __restrict__ bias,
              __half* __restrict__ Cf16,
              int M, int N, int K)
{
    extern __shared__ __align__(1024) char smem[];
    const uint32_t sbase = (uint32_t)__cvta_generic_to_shared(smem);

    const int tid  = threadIdx.x;
    const int lane = tid & 31;
    const int wid  = tid >> 5;
    const int wm   = (wid & 3) * 32;
    const int wn   = (wid >> 2) * 64;
    const int bm   = blockIdx.y * 128;
    const int bn   = blockIdx.x * 128;

    const int lr8   = lane & 7;
    const int g     = lane >> 3;
    const int mrow  = (g & 1) * 8;
    const int kcolB = (g >> 1) * 16;

    uint32_t aRow[2], aXm[2], bRow[4], bXm[4];
    #pragma unroll
    for (int mi = 0; mi < 2; mi++) {
        const uint32_t rB = (uint32_t)(wm + mi * 16 + mrow + lr8) * 128;
        aRow[mi] = rB;
        aXm[mi]  = (rB >> 3) & 0x70;
    }
    #pragma unroll
    for (int p = 0; p < 4; p++) {
        const uint32_t rB = (uint32_t)(wn + p * 16 + mrow + lr8) * 128;
        bRow[p] = B128_OFF + rB;
        bXm[p]  = (rB >> 3) & 0x70;
    }

    float acc[2][8][4];
    #pragma unroll
    for (int i = 0; i < 2; i++)
        #pragma unroll
        for (int j = 0; j < 8; j++)
            #pragma unroll
            for (int v = 0; v < 4; v++) acc[i][j][v] = 0.f;

    const int nT = K / 64;

    auto stage = [&](int lt) {
        const uint32_t sb = sbase + (uint32_t)(lt % 3) * STAGE128;
        const int k0 = lt * 64;
        #pragma unroll
        for (int i = 0; i < 4; i++) {
            const int lin = tid + i * 256;
            const int r = lin >> 3;
            const int c = lin & 7;
            const uint32_t off = (uint32_t)r * 128 + (uint32_t)c * 16;
            const uint32_t sw = off ^ ((off >> 3) & 0x70);
            const bool pa = (bm + r) < M;
            cp16(sb + sw, A + (size_t)(bm + r) * K + k0 + c * 8, pa);
        }
        #pragma unroll
        for (int i = 0; i < 4; i++) {
            const int lin = tid + i * 256;
            const int r = lin >> 3;
            const int c = lin & 7;
            const uint32_t off = (uint32_t)r * 128 + (uint32_t)c * 16;
            const uint32_t sw = off ^ ((off >> 3) & 0x70);
            cp16(sb + B128_OFF + sw, W + (size_t)(bn + r) * K + k0 + c * 8, true);
        }
        cp_commit();
    };

    stage(0);
    stage(1);

    for (int kt = 0; kt < nT; kt++) {
        if (kt + 1 < nT) cp_wait<1>();
        else             cp_wait<0>();
        __syncthreads();
        if (kt + 2 < nT) stage(kt + 2);

        const uint32_t s0 = sbase + (uint32_t)(kt % 3) * STAGE128;

        #pragma unroll
        for (int ks = 0; ks < 64; ks += 16) {
            const uint32_t col = (uint32_t)(ks * 2) + kcolB;
            uint32_t ah[2][4];
            #pragma unroll
            for (int mi = 0; mi < 2; mi++)
                ldsm4(ah[mi], s0 + aRow[mi] + (col ^ aXm[mi]));
            #pragma unroll
            for (int p = 0; p < 4; p++) {
                uint32_t bh[4];
                ldsm4(bh, s0 + bRow[p] + (col ^ bXm[p]));
                #pragma unroll
                for (int mi = 0; mi < 2; mi++) {
                    mma_fp16(acc[mi][2 * p],     ah[mi], bh[0], bh[2]);
                    mma_fp16(acc[mi][2 * p + 1], ah[mi], bh[1], bh[3]);
                }
            }
        }
    }

    const int lq = (lane & 3) * 2;
    const int lr = lane >> 2;
    #pragma unroll
    for (int mi = 0; mi < 2; mi++) {
        #pragma unroll
        for (int ni = 0; ni < 8; ni++) {
            const int m0 = bm + wm + mi * 16 + lr;
            const int n  = bn + wn + ni * 8 + lq;
            const float bv0 = __ldg(bias + n), bv1 = __ldg(bias + n + 1);
            #pragma unroll
            for (int h = 0; h < 2; h++) {
                const int m = m0 + h * 8;
                if (m < M) {
                    float x0 = fmaxf(acc[mi][ni][2 * h]     + bv0, 0.f);
                    float x1 = fmaxf(acc[mi][ni][2 * h + 1] + bv1, 0.f);
                    *reinterpret_cast<uint32_t*>(Cf16 + (size_t)m * N + n) =
                        pack_h2(__float2half_rn(x0), __float2half_rn(x1));
                }
            }
        }
    }
}

// ============================================================================
// gemmh<OUT>: fp16 single-term, 128x64 tile (R13-proven).
// ============================================================================
#define BH_OFF 16384
#define STAGEH 24576
#define SMEMH (4 * STAGEH)

template <int OUT>
__global__ __launch_bounds__(256, 2)
void gemmh(const __half* __restrict__ A,
           const __half* __restrict__ W,
           const float* __restrict__ bias,
           __half* __restrict__ Cf16,
           __nv_bfloat16* __restrict__ Chi,
           __nv_bfloat16* __restrict__ Clo,
           int M, int N, int K)
{
    extern __shared__ __align__(1024) char smem[];
    const uint32_t sbase = (uint32_t)__cvta_generic_to_shared(smem);

    const int tid  = threadIdx.x;
    const int lane = tid & 31;
    const int wid  = tid >> 5;
    const int wm   = (wid & 3) * 32;
    const int wn   = (wid >> 2) * 32;
    const int bm   = blockIdx.y * 128;
    const int bn   = blockIdx.x * 64;

    const int lr8   = lane & 7;
    const int g     = lane >> 3;
    const int mrow  = (g & 1) * 8;
    const int kcolB = (g >> 1) * 16;

    uint32_t aRow[2], aXm[2], bRow[2], bXm[2];
    #pragma unroll
    for (int mi = 0; mi < 2; mi++) {
        const uint32_t rB = (uint32_t)(wm + mi * 16 + mrow + lr8) * 128;
        aRow[mi] = rB;
        aXm[mi]  = (rB >> 3) & 0x70;
    }
    #pragma unroll
    for (int p = 0; p < 2; p++) {
        const uint32_t rB = (uint32_t)(wn + p * 16 + mrow + lr8) * 128;
        bRow[p] = BH_OFF + rB;
        bXm[p]  = (rB >> 3) & 0x70;
    }

    float acc[2][4][4];
    #pragma unroll
    for (int i = 0; i < 2; i++)
        #pragma unroll
        for (int j = 0; j < 4; j++)
            #pragma unroll
            for (int v = 0; v < 4; v++) acc[i][j][v] = 0.f;

    const int nT = K / 64;

    auto stage = [&](int lt) {
        const uint32_t sb = sbase + (uint32_t)(lt & 3) * STAGEH;
        const int k0 = lt * 64;
        #pragma unroll
        for (int i = 0; i < 4; i++) {
            const int lin = tid + i * 256;
            const int r = lin >> 3;
            const int c = lin & 7;
            const uint32_t off = (uint32_t)r * 128 + (uint32_t)c * 16;
            const uint32_t sw = off ^ ((off >> 3) & 0x70);
            const bool pa = (bm + r) < M;
            cp16(sb + sw, A + (size_t)(bm + r) * K + k0 + c * 8, pa);
        }
        #pragma unroll
        for (int i = 0; i < 2; i++) {
            const int lin = tid + i * 256;
            const int r = lin >> 3;
            const int c = lin & 7;
            const uint32_t off = (uint32_t)r * 128 + (uint32_t)c * 16;
            const uint32_t sw = off ^ ((off >> 3) & 0x70);
            cp16(sb + BH_OFF + sw, W + (size_t)(bn + r) * K + k0 + c * 8, true);
        }
        cp_commit();
    };

    stage(0);
    stage(1);
    stage(2);

    for (int kt = 0; kt < nT; kt++) {
        if (kt + 2 <= nT - 1)      cp_wait<2>();
        else if (kt + 1 <= nT - 1) cp_wait<1>();
        else                       cp_wait<0>();
        __syncthreads();
        if (kt + 3 < nT) stage(kt + 3);

        const uint32_t s0 = sbase + (uint32_t)(kt & 3) * STAGEH;

        #pragma unroll
        for (int ks = 0; ks < 64; ks += 16) {
            const uint32_t col = (uint32_t)(ks * 2) + kcolB;
            uint32_t ah[2][4], bh[2][4];
            #pragma unroll
            for (int mi = 0; mi < 2; mi++)
                ldsm4(ah[mi], s0 + aRow[mi] + (col ^ aXm[mi]));
            #pragma unroll
            for (int p = 0; p < 2; p++)
                ldsm4(bh[p], s0 + bRow[p] + (col ^ bXm[p]));
            #pragma unroll
            for (int mi = 0; mi < 2; mi++)
                #pragma unroll
                for (int ni = 0; ni < 4; ni++) {
                    const int p = ni >> 1, q = ni & 1;
                    mma_fp16(acc[mi][ni], ah[mi], bh[p][q], bh[p][q + 2]);
                }
        }
    }

    const int lq = (lane & 3) * 2;
    const int lr = lane >> 2;
    #pragma unroll
    for (int mi = 0; mi < 2; mi++) {
        #pragma unroll
        for (int ni = 0; ni < 4; ni++) {
            const int m0 = bm + wm + mi * 16 + lr;
            const int n  = bn + wn + ni * 8 + lq;
            const float bv0 = __ldg(bias + n), bv1 = __ldg(bias + n + 1);
            #pragma unroll
            for (int h = 0; h < 2; h++) {
                const int m = m0 + h * 8;
                if (m < M) {
                    float x0 = fmaxf(acc[mi][ni][2 * h]     + bv0, 0.f);
                    float x1 = fmaxf(acc[mi][ni][2 * h + 1] + bv1, 0.f);
                    if (OUT == 0) {
                        *reinterpret_cast<uint32_t*>(Cf16 + (size_t)m * N + n) =
                            pack_h2(__float2half_rn(x0), __float2half_rn(x1));
                    } else {
                        __nv_bfloat16 h0 = __float2bfloat16(x0);
                        __nv_bfloat16 h1 = __float2bfloat16(x1);
                        __nv_bfloat16 l0 = __float2bfloat16(x0 - __bfloat162float(h0));
                        __nv_bfloat16 l1 = __float2bfloat16(x1 - __bfloat162float(h1));
                        *reinterpret_cast<uint32_t*>(Chi + (size_t)m * N + n) = pack_bf2(h0, h1);
                        *reinterpret_cast<uint32_t*>(Clo + (size_t)m * N + n) = pack_bf2(l0, l1);
                    }
                }
            }
        }
    }
}

// ============================================================================
// gemm_small_fused: bf16x3 split-K(4) with fused finalize (R12-proven).
// ============================================================================
#define A_T3 4096
#define STAGE3 12288
#define SMEM3 (3 * STAGE3)

__global__ __launch_bounds__(128, 4)
void gemm_small_fused(const __nv_bfloat16* __restrict__ Ahi,
                      const __nv_bfloat16* __restrict__ Alo,
                      const __nv_bfloat16* __restrict__ Whi,
                      const __nv_bfloat16* __restrict__ Wlo,
                      const float* __restrict__ bias,
                      float* __restrict__ part,
                      unsigned* __restrict__ ticket,
                      __nv_bfloat16* __restrict__ Chi,
                      __nv_bfloat16* __restrict__ Clo,
                      int M, int N, int K)
{
    extern __shared__ __align__(1024) char smem[];
    const uint32_t sbase = (uint32_t)__cvta_generic_to_shared(smem);

    const int tid  = threadIdx.x;
    const int lane = tid & 31;
    const int wid  = tid >> 5;
    const int wm   = (wid & 1) * 16;
    const int wn   = (wid >> 1) * 32;
    const int bm   = blockIdx.y * 32;
    const int bn   = blockIdx.x * 64;
    const int kbase = blockIdx.z * (K / KSPLIT);

    const int lr8   = lane & 7;
    const int g     = lane >> 3;
    const int mrow  = (g & 1) * 8;
    const int kcolB = (g >> 1) * 16;

    uint32_t aRowB, aXm, bRow[2], bXm[2];
    {
        const uint32_t rB = (uint32_t)(wm + mrow + lr8) * 128;
        aRowB = rB;
        aXm   = (rB >> 3) & 0x70;
    }
    #pragma unroll
    for (int p = 0; p < 2; p++) {
        const uint32_t rB = (uint32_t)(wn + p * 16 + mrow + lr8) * 128;
        bRow[p] = A_T3 + rB;
        bXm[p]  = (rB >> 3) & 0x70;
    }

    float acc[4][4];
    #pragma unroll
    for (int j = 0; j < 4; j++)
        #pragma unroll
        for (int v = 0; v < 4; v++) acc[j][v] = 0.f;

    const int nT = (K / KSPLIT) / 32;

    auto stage = [&](int lt) {
        const uint32_t sb = sbase + (uint32_t)(lt % 3) * STAGE3;
        const int k0 = kbase + lt * 32;
        #pragma unroll
        for (int i = 0; i < 2; i++) {
            const int lin = tid + i * 128;
            const int r = lin >> 3;
            const int c = lin & 7;
            const uint32_t off = (uint32_t)r * 128 + (uint32_t)c * 16;
            const uint32_t sw = off ^ ((off >> 3) & 0x70);
            const bool pa = (bm + r) < M;
            const __nv_bfloat16* src = (c < 4) ? Ahi : Alo;
            cp16(sb + sw, src + (size_t)(bm + r) * K + k0 + (c & 3) * 8, pa);
        }
        #pragma unroll
        for (int i = 0; i < 4; i++) {
            const int lin = tid + i * 128;
            const int r = lin >> 3;
            const int c = lin & 7;
            const uint32_t off = (uint32_t)r * 128 + (uint32_t)c * 16;
            const uint32_t sw = off ^ ((off >> 3) & 0x70);
            const __nv_bfloat16* src = (c < 4) ? Whi : Wlo;
            cp16(sb + A_T3 + sw, src + (size_t)(bn + r) * K + k0 + (c & 3) * 8, true);
        }
        cp_commit();
    };

    stage(0);
    stage(1);

    for (int kt = 0; kt < nT; kt++) {
        if (kt + 1 < nT) cp_wait<1>();
        else             cp_wait<0>();
        __syncthreads();
        if (kt + 2 < nT) stage(kt + 2);

        const uint32_t s0 = sbase + (uint32_t)(kt % 3) * STAGE3;

        #pragma unroll
        for (int ks = 0; ks < 32; ks += 16) {
            const uint32_t colH = (uint32_t)(ks * 2) + kcolB;
            const uint32_t colL = 64u + (uint32_t)(ks * 2) + kcolB;
            uint32_t ah[4], al[4], bh[2][4], bl[2][4];
            ldsm4(ah, s0 + aRowB + (colH ^ aXm));
            ldsm4(al, s0 + aRowB + (colL ^ aXm));
            #pragma unroll
            for (int p = 0; p < 2; p++) {
                ldsm4(bh[p], s0 + bRow[p] + (colH ^ bXm[p]));
                ldsm4(bl[p], s0 + bRow[p] + (colL ^ bXm[p]));
            }
            #pragma unroll
            for (int ni = 0; ni < 4; ni++) {
                const int p = ni >> 1, q = ni & 1;
                mma_bf16(acc[ni], ah, bh[p][q], bh[p][q + 2]);
                mma_bf16(acc[ni], ah, bl[p][q], bl[p][q + 2]);
                mma_bf16(acc[ni], al, bh[p][q], bh[p][q + 2]);
            }
        }
    }

    const int lq = (lane & 3) * 2;
    const int lr = lane >> 2;
    #pragma unroll
    for (int ni = 0; ni < 4; ni++) {
        const int m0 = bm + wm + lr;
        const int n  = bn + wn + ni * 8 + lq;
        #pragma unroll
        for (int h = 0; h < 2; h++) {
            const int m = m0 + h * 8;
            if (m < M) {
                float* dst = part + ((size_t)blockIdx.z * M + m) * N + n;
                dst[0] = acc[ni][2 * h];
                dst[1] = acc[ni][2 * h + 1];
            }
        }
    }

    __threadfence();
    __syncthreads();
    __shared__ unsigned s_old;
    const int tileId = (int)blockIdx.y * (int)gridDim.x + (int)blockIdx.x;
    if (tid == 0) s_old = atomicAdd(&ticket[tileId], 1u);
    __syncthreads();
    if (s_old == KSPLIT - 1) {
        __threadfence();
        for (int idx = tid * 2; idx < 32 * 64; idx += 256) {
            const int lm = idx >> 6;
            const int ln = idx & 63;
            const int m = bm + lm;
            if (m >= M) break;
            const int n = bn + ln;
            float s0 = 0.f, s1 = 0.f;
            #pragma unroll
            for (int z = 0; z < KSPLIT; z++) {
                const float* p = part + ((size_t)z * M + m) * N + n;
                s0 += p[0];
                s1 += p[1];
            }
            float x0 = fmaxf(s0 + __ldg(bias + n), 0.f);
            float x1 = fmaxf(s1 + __ldg(bias + n + 1), 0.f);
            __nv_bfloat16 h0 = __float2bfloat16(x0);
            __nv_bfloat16 h1 = __float2bfloat16(x1);
            __nv_bfloat16 l0 = __float2bfloat16(x0 - __bfloat162float(h0));
            __nv_bfloat16 l1 = __float2bfloat16(x1 - __bfloat162float(h1));
            *reinterpret_cast<uint32_t*>(Chi + (size_t)m * N + n) = pack_bf2(h0, h1);
            *reinterpret_cast<uint32_t*>(Clo + (size_t)m * N + n) = pack_bf2(l0, l1);
        }
        if (tid == 0) ticket[tileId] = 0;
    }
}

// Root projection
__global__ void proj_kernel(const __nv_bfloat16* __restrict__ hhi,
                            const __nv_bfloat16* __restrict__ hlo,
                            const float* __restrict__ Wp,
                            const float* __restrict__ bp,
                            float* __restrict__ out)
{
    const int w    = threadIdx.x >> 5;
    const int lane = threadIdx.x & 31;
    float s = 0.f;
    for (int k = lane; k < 512; k += 32) {
        const float hv = __bfloat162float(hhi[k]) + __bfloat162float(hlo[k]);
        s = fmaf(hv, Wp[w * 512 + k], s);
    }
    #pragma unroll
    for (int o = 16; o > 0; o >>= 1)
        s += __shfl_xor_sync(0xffffffffu, s, o);
    if (lane == 0) out[w] = s + bp[w];
}

extern "C" void kernel_launch(void* const* d_in, const int* in_sizes, int n_in,
                              void* d_out, int out_size)
{
    const float* leaf  = (const float*)d_in[0];
    const float* Wemb  = (const float*)d_in[1];
    const float* bemb  = (const float*)d_in[2];
    const float* Wcomb = (const float*)d_in[3];
    const float* bcomb = (const float*)d_in[4];
    const float* Wproj = (const float*)d_in[5];
    const float* bproj = (const float*)d_in[6];
    float* out = (float*)d_out;

    __half *leaf16, *We16, *Wc16, *P16, *Q16;
    __nv_bfloat16 *Wcb_h, *Wcb_l, *hB, *lB, *hC, *lC;
    float* part;
    unsigned* ticket;
    cudaGetSymbolAddress((void**)&leaf16, g_leaf16);
    cudaGetSymbolAddress((void**)&We16, g_We16);
    cudaGetSymbolAddress((void**)&Wc16, g_Wc16);
    cudaGetSymbolAddress((void**)&Wcb_h, g_Wcb_h);
    cudaGetSymbolAddress((void**)&Wcb_l, g_Wcb_l);
    cudaGetSymbolAddress((void**)&P16, g_P16);
    cudaGetSymbolAddress((void**)&Q16, g_Q16);
    cudaGetSymbolAddress((void**)&hB, g_hB);
    cudaGetSymbolAddress((void**)&lB, g_lB);
    cudaGetSymbolAddress((void**)&hC, g_hC);
    cudaGetSymbolAddress((void**)&lC, g_lC);
    cudaGetSymbolAddress((void**)&part, g_part);
    cudaGetSymbolAddress((void**)&ticket, g_ticket);

    cudaFuncSetAttribute(gemmh128,
                         cudaFuncAttributeMaxDynamicSharedMemorySize, SMEM128);
    cudaFuncSetAttribute(gemmh<0>,
                         cudaFuncAttributeMaxDynamicSharedMemorySize, SMEMH);
    cudaFuncSetAttribute(gemmh<1>,
                         cudaFuncAttributeMaxDynamicSharedMemorySize, SMEMH);
    cudaFuncSetAttribute(gemm_small_fused,
                         cudaFuncAttributeMaxDynamicSharedMemorySize, SMEM3);

    // ---- convert/split inputs ----
    conv_f16<<<4096, 256>>>((const float4*)leaf, (uint2*)leaf16, 8192 * 4096 / 4);
    conv_f16<<<512, 256>>>((const float4*)Wemb, (uint2*)We16, 512 * 4096 / 4);
    split_wc<<<128, 256>>>((const float4*)Wcomb, (uint2*)Wc16,
                           (uint2*)Wcb_h, (uint2*)Wcb_l, 512 * 1024 / 4);

    // ---- leaf -> P16 (128x128 tiles, 256 CTAs) ----
    {
        dim3 grid(512 / 128, 8192 / 128);
        gemmh128<<<grid, 256, SMEM128>>>(leaf16, We16, bemb, P16,
                                         8192, 512, 4096);
    }
    // ---- m = 4096 -> Q16 (128x64 tiles, 256 CTAs) ----
    {
        dim3 grid(512 / 64, 4096 / 128);
        gemmh<0><<<grid, 256, SMEMH>>>(P16, Wc16, bcomb,
                                       Q16, nullptr, nullptr, 4096, 512, 1024);
    }
    // ---- m = 2048 -> P16 ----
    {
        dim3 grid(512 / 64, 2048 / 128);
        gemmh<0><<<grid, 256, SMEMH>>>(Q16, Wc16, bcomb,
                                       P16, nullptr, nullptr, 2048, 512, 1024);
    }
    // ---- m = 1024 -> bf16 pair hB/lB ----
    {
        dim3 grid(512 / 64, 1024 / 128);
        gemmh<1><<<grid, 256, SMEMH>>>(P16, Wc16, bcomb,
                                       nullptr, hB, lB, 1024, 512, 1024);
    }

    // ---- tail m = 512..1: bf16x3 split-K(4) with fused finalize ----
    __nv_bfloat16 *cur_h = hB, *cur_l = lB, *nxt_h = hC, *nxt_l = lC;
    for (int m = 512; m >= 1; m >>= 1) {
        dim3 grid(512 / 64, (m + 31) / 32, KSPLIT);
        gemm_small_fused<<<grid, 128, SMEM3>>>(cur_h, cur_l, Wcb_h, Wcb_l,
                                               bcomb, part, ticket,
                                               nxt_h, nxt_l, m, 512, 1024);
        __nv_bfloat16* t;
        t = cur_h; cur_h = nxt_h; nxt_h = t;
        t = cur_l; cur_l = nxt_l; nxt_l = t;
    }

    proj_kernel<<<1, 64>>>(cur_h, cur_l, Wproj, bproj, out);
}